// round 2
// baseline (speedup 1.0000x reference)
#include <cuda_runtime.h>

// CTC batch cost, log2-domain forward algorithm.
// B=256, T=512, C=128, U=48 -> S=97 extended states. Blank = C-1 = 127.
// One CTA handles 2 batch items: threads [0,128) -> batch b0, [128,256) -> b1.
// Each thread owns one state s (s<97) and one class column for the row load.

#define Bc 256
#define Tc 512
#define Cc 128
#define Uc 48
#define Sc 97            // 2*U+1
#define BLANKC 127
#define NEGF (-1e30f)
#define EPSF 1e-7f
#define PF 8             // prefetch depth (register ring)

__device__ __forceinline__ float ex2f_(float x) {
    float y; asm("ex2.approx.f32 %0, %1;" : "=f"(y) : "f"(x)); return y;
}
__device__ __forceinline__ float lg2f_(float x) {
    float y; asm("lg2.approx.f32 %0, %1;" : "=f"(y) : "f"(x)); return y;
}

__global__ __launch_bounds__(256, 2)
void ctc_fwd_kernel(const void* __restrict__ yt_raw,
                    const float* __restrict__ y_pred,
                    float* __restrict__ out)
{
    __shared__ int   s_ext[2][Sc];
    __shared__ unsigned char s_skip[2][Sc];
    __shared__ float s_alpha[2][2][Sc + 1];   // [batch-in-block][buffer][state]
    __shared__ float s_row[2][2][Cc];         // [batch-in-block][buffer][class] log2-probs
    __shared__ int   s_is64;

    const int tid  = threadIdx.x;
    const int lb   = tid >> 7;       // 0/1: which batch item in this block
    const int ltid = tid & 127;      // lane within the batch sub-block
    const int b    = blockIdx.x * 2 + lb;

    // ---- label dtype detection (int32 vs int64), deterministic ----
    if (tid == 0) s_is64 = 1;
    __syncthreads();
    {
        const long long* p64 = (const long long*)yt_raw;   // 512B probe, safe in both layouts
        for (int i = tid; i < 64; i += 256) {
            long long v = p64[i];
            if (v < 0 || v > 127) atomicAnd(&s_is64, 0);
        }
    }
    __syncthreads();
    const bool is64 = (s_is64 != 0);

    // ---- build extended label sequence + skip mask ----
    const int*       p32 = (const int*)yt_raw;
    const long long* p64 = (const long long*)yt_raw;
    if (ltid < Sc) {
        int lab;
        if (ltid & 1) {
            int u = ltid >> 1;
            lab = is64 ? (int)p64[b * Uc + u] : p32[b * Uc + u];
        } else {
            lab = BLANKC;
        }
        s_ext[lb][ltid] = lab;
    }
    __syncthreads();
    bool mysk = false;
    int  myext = 0;
    if (ltid < Sc) {
        int e = s_ext[lb][ltid];
        bool ok = (e != BLANKC) && ((ltid < 2) ? true : (e != s_ext[lb][ltid - 2]));
        s_skip[lb][ltid] = ok ? 1 : 0;
        mysk = ok;
        myext = e;
    }

    // ---- t = 0: load row, init alpha ----
    const float* gp = y_pred + (size_t)b * Tc * Cc + ltid;  // this thread's class column
    float p0 = gp[0];
    s_row[lb][0][ltid] = lg2f_(p0 + EPSF);
    __syncthreads();
    if (ltid < Sc) {
        s_alpha[lb][0][ltid] = (ltid < 2) ? s_row[lb][0][myext] : NEGF;
    }

    // ---- prefetch rows 1..PF into a register ring ----
    float pbuf[PF];
#pragma unroll
    for (int j = 0; j < PF; j++) pbuf[j] = gp[(size_t)(1 + j) * Cc];

    // ---- main recursion: 1 __syncthreads per timestep, double-buffered smem ----
    for (int t0 = 1; t0 < Tc; t0 += PF) {
#pragma unroll
        for (int j = 0; j < PF; j++) {
            const int t = t0 + j;
            if (t < Tc) {
                const int cur = t & 1;
                const int prv = cur ^ 1;
                float l2 = lg2f_(pbuf[j] + EPSF);
                if (t + PF < Tc) pbuf[j] = gp[(size_t)(t + PF) * Cc];  // refill ring
                s_row[lb][cur][ltid] = l2;
                __syncthreads();
                if (ltid < Sc) {
                    float a  = s_alpha[lb][prv][ltid];
                    float a1 = (ltid >= 1) ? s_alpha[lb][prv][ltid - 1] : NEGF;
                    float a2 = (ltid >= 2 && mysk) ? s_alpha[lb][prv][ltid - 2] : NEGF;
                    float m  = fmaxf(a, fmaxf(a1, a2));
                    float sum = ex2f_(a - m) + ex2f_(a1 - m) + ex2f_(a2 - m);
                    s_alpha[lb][cur][ltid] = m + lg2f_(sum) + s_row[lb][cur][myext];
                }
            }
        }
    }

    __syncthreads();
    if (ltid == 0) {
        const int lastbuf = (Tc - 1) & 1;
        float x = s_alpha[lb][lastbuf][Sc - 1];
        float y = s_alpha[lb][lastbuf][Sc - 2];
        float m = fmaxf(x, y);
        float ll2 = m + lg2f_(ex2f_(x - m) + ex2f_(y - m));
        out[b] = -ll2 * 0.69314718055994530942f;   // log2 -> natural log
    }
}

extern "C" void kernel_launch(void* const* d_in, const int* in_sizes, int n_in,
                              void* d_out, int out_size)
{
    (void)in_sizes; (void)n_in; (void)out_size;
    const void*  y_true = d_in[0];
    const float* y_pred = (const float*)d_in[1];
    float* out = (float*)d_out;
    ctc_fwd_kernel<<<Bc / 2, 256>>>(y_true, y_pred, out);
}